// round 8
// baseline (speedup 1.0000x reference)
#include <cuda_runtime.h>

// Problem constants
#define BB 4
#define TT 16
#define NN 512
#define FF 5
#define HH 64
#define SS 2048           // B*N sequences
#define GG 256            // 4*H gates
#define R4 206            // RR/4 float4 per relation row
#define NSM 152           // GB300 SM count -> persistent 1 CTA/SM
#define NPAIR (NN*NN)     // 262144 relation pairs
#define NCHUNK (NPAIR/32) // 8192 32-pair chunks
#define TPC 2             // chunks per ticket
#define ARRS 264          // arr row stride (floats), 16B-aligned, skewed
// h k-major layout with 16B skew per 16-k block: conflict-free kb access
#define KOFF(k) ((k)*8 + ((k)>>4)*4)

// Scratch (device globals; no allocation allowed).
// g_relw: only entries with rel_mask==0 are ever written; masked entries stay
// 0.0 (static zero-init) and are annihilated by the -1e9 mask in the softmax,
// exactly as in the reference (exp underflows to 0 in fp32). Deterministic.
__device__ float g_relw[NPAIR];
__device__ float g_tail[SS];      // leaky(out . fc3_w + fc3_b)
__device__ float g_q[SS];         // out . pred_w[64:128]
__device__ float g_p0[SS];        // out . pred_w[0:64]

// Grid-wide barrier (generation-based; replay-safe) + phase-1 work ticket.
__device__ unsigned int g_bar_count = 0;
__device__ unsigned int g_bar_gen   = 0;
__device__ unsigned int g_ticket    = 0;   // reset after barrier each launch

__device__ __forceinline__ float leaky(float v) { return v > 0.f ? v : 0.01f * v; }
// fast activations (err ~1e-6, fine at 1e-3 tolerance)
__device__ __forceinline__ float sigm(float v)   { return __fdividef(1.f, 1.f + __expf(-v)); }
__device__ __forceinline__ float tanhft(float v) { return 1.f - __fdividef(2.f, __expf(2.f * v) + 1.f); }

__device__ __forceinline__ void barn(int id, int cnt) {
    asm volatile("bar.sync %0, %1;" :: "r"(id), "r"(cnt) : "memory");
}

// packed f32x2 fma: d = a*b + d (elementwise on the two fp32 halves)
__device__ __forceinline__ void fma2(unsigned long long& d,
                                     unsigned long long a,
                                     unsigned long long b) {
    asm("fma.rn.f32x2 %0, %1, %2, %3;" : "=l"(d) : "l"(a), "l"(b), "l"(d));
}
__device__ __forceinline__ unsigned long long pack2(float lo, float hi) {
    unsigned long long r;
    asm("mov.b64 %0, {%1, %2};" : "=l"(r) : "f"(lo), "f"(hi));
    return r;
}
__device__ __forceinline__ void unpack2(unsigned long long a, float& lo, float& hi) {
    asm("mov.b64 {%0, %1}, %2;" : "=f"(lo), "=f"(hi) : "l"(a));
}
__device__ __forceinline__ float sum2(unsigned long long a) {
    float lo, hi;
    unpack2(a, lo, hi);
    return lo + hi;
}
#define D2L __double_as_longlong

// One 824-length dot product, 32 lanes cooperating; returns lane-0 sum.
__device__ __forceinline__ float row_dot(const float4* __restrict__ row,
                                         const float4* __restrict__ wsm,
                                         int lane) {
    float4 a0 = __ldcs(row + lane);
    float4 a1 = __ldcs(row + lane + 32);
    float4 a2 = __ldcs(row + lane + 64);
    float4 a3 = __ldcs(row + lane + 96);
    float4 a4 = __ldcs(row + lane + 128);
    float4 a5 = __ldcs(row + lane + 160);
    float4 a6 = (lane < 14) ? __ldcs(row + lane + 192)
                            : make_float4(0.f, 0.f, 0.f, 0.f);
    float s = 0.f;
    float4 w;
    w = wsm[lane];       s += a0.x*w.x + a0.y*w.y + a0.z*w.z + a0.w*w.w;
    w = wsm[lane + 32];  s += a1.x*w.x + a1.y*w.y + a1.z*w.z + a1.w*w.w;
    w = wsm[lane + 64];  s += a2.x*w.x + a2.y*w.y + a2.z*w.z + a2.w*w.w;
    w = wsm[lane + 96];  s += a3.x*w.x + a3.y*w.y + a3.z*w.z + a3.w*w.w;
    w = wsm[lane + 128]; s += a4.x*w.x + a4.y*w.y + a4.z*w.z + a4.w*w.w;
    w = wsm[lane + 160]; s += a5.x*w.x + a5.y*w.y + a5.z*w.z + a5.w*w.w;
    if (lane < 14) {
        w = wsm[lane + 192];
        s += a6.x*w.x + a6.y*w.y + a6.z*w.z + a6.w*w.w;
    }
#pragma unroll
    for (int o = 16; o; o >>= 1) s += __shfl_xor_sync(0xffffffffu, s, o);
    return s;
}

// ---------------------------------------------------------------------------
// LSTM engine v2: 256 threads, up to 8 sequences, register-blocked recurrence.
// Thread tile = 4 gates x 8 seqs x 16 k. h stored k-major (skewed) in smem;
// k-partials reduced with 2 shfl_xor rounds; lane-group kb then handles
// x-part + activation + store for seq-pair kb. Wih/bias read from smem.
// ---------------------------------------------------------------------------
__device__ __forceinline__ void lstm_engine(
    int t256, int sbase, int ns,
    const float* __restrict__ x,
    const float* __restrict__ Whh_f,
    const float* __restrict__ Wih_b,
    const float* __restrict__ bih_b, const float* __restrict__ bhh_b,
    const float* __restrict__ fc0_w, const float* __restrict__ fc0_b,
    const float* __restrict__ fc3_w, const float* __restrict__ fc3_b,
    const float* __restrict__ pred_w,
    const float* __restrict__ wihs,   // smem [GG*FF]
    const float* __restrict__ bsumS,  // smem [GG] (bih_f+bhh_f)
    float* __restrict__ xs,      // [8*TT*FF]
    float* __restrict__ hsm,     // [544] k-major skewed
    float* __restrict__ arr,     // [8*ARRS]
    float* __restrict__ last,    // [8*2*HH]
    float* __restrict__ outb,    // [8*HH]
    int barid)
{
    const int w    = t256 >> 5, lane = t256 & 31;
    const int kb   = lane >> 3, gl   = lane & 7;
    const int G0   = w * 32 + gl * 4;      // this thread's 4 gates
    const int kbase = kb * 16;             // this thread's k range
    const int gtype = G0 >> 6;             // uniform per warp
    const int u = t256 & 63, su = t256 >> 6;  // update role: (su,u),(su+4,u)
    const int s0 = 2 * kb;                 // activation role: seqs s0, s0+1

    // Recurrent weights register-resident: whr[g][j] = Whh[(G0+g)*64+kbase+j]
    float whr[4][16];
#pragma unroll
    for (int g = 0; g < 4; g++) {
        const float4* wr = (const float4*)(Whh_f + (G0 + g) * HH + kbase);
#pragma unroll
        for (int q = 0; q < 4; q++) {
            float4 v = wr[q];
            whr[g][4*q] = v.x; whr[g][4*q+1] = v.y;
            whr[g][4*q+2] = v.z; whr[g][4*q+3] = v.w;
        }
    }

    // Stage x (zero-fill inactive seqs), zero h
    for (int i = t256; i < 8 * TT * FF; i += 256) {
        float v = 0.f;
        if (i < ns * TT * FF) {
            int s = i / (TT * FF), r = i - s * (TT * FF);
            int t = r / FF, f = r - t * FF;
            int sg = sbase + s;
            int b = sg >> 9, n = sg & (NN - 1);
            v = x[((b * TT + t) * NN + n) * FF + f];
        }
        xs[i] = v;
    }
    for (int i = t256; i < 544; i += 256) hsm[i] = 0.f;
    float creg0 = 0.f, creg1 = 0.f;
    barn(barid, 256);

    // ---- forward recurrence ----
#pragma unroll 1
    for (int t = 0; t < TT; t++) {
        unsigned long long acc[4][4];      // [gate][seq-pair]
#pragma unroll
        for (int g = 0; g < 4; g++)
#pragma unroll
            for (int sp = 0; sp < 4; sp++) acc[g][sp] = 0ull;

#pragma unroll
        for (int j = 0; j < 16; j++) {
            const double2* hp = (const double2*)(hsm + KOFF(kbase + j));
            double2 pA = hp[0];            // seqs 0,1 | 2,3
            double2 pB = hp[1];            // seqs 4,5 | 6,7
#pragma unroll
            for (int g = 0; g < 4; g++) {
                unsigned long long wp = pack2(whr[g][j], whr[g][j]);
                fma2(acc[g][0], D2L(pA.x), wp);
                fma2(acc[g][1], D2L(pA.y), wp);
                fma2(acc[g][2], D2L(pB.x), wp);
                fma2(acc[g][3], D2L(pB.y), wp);
            }
        }

        // k-reduction over the 4 kb lane-groups (lane bits 3,4)
        float gv0[4], gv1[4];
#pragma unroll
        for (int g = 0; g < 4; g++) {
#pragma unroll
            for (int sp = 0; sp < 4; sp++) {
                float lo, hi;
                unpack2(acc[g][sp], lo, hi);
                lo += __shfl_xor_sync(0xffffffffu, lo, 8);
                hi += __shfl_xor_sync(0xffffffffu, hi, 8);
                lo += __shfl_xor_sync(0xffffffffu, lo, 16);
                hi += __shfl_xor_sync(0xffffffffu, hi, 16);
                if (sp == kb) { gv0[g] = lo; gv1[g] = hi; }
            }
        }

        // x-part + bias + activation for seqs s0, s0+1 (lane-group kb's pair)
        {
            const float* xtA = xs + s0 * (TT * FF) + t * FF;
            const float* xtB = xtA + (TT * FF);
            float o0[4], o1[4];
#pragma unroll
            for (int g = 0; g < 4; g++) {
                float b = bsumS[G0 + g];
                float a0 = gv0[g] + b;
                float a1 = gv1[g] + b;
                const float* wi = wihs + (G0 + g) * FF;
#pragma unroll
                for (int f = 0; f < FF; f++) {
                    float wv = wi[f];
                    a0 += xtA[f] * wv;
                    a1 += xtB[f] * wv;
                }
                o0[g] = (gtype == 2) ? tanhft(a0) : sigm(a0);
                o1[g] = (gtype == 2) ? tanhft(a1) : sigm(a1);
            }
            *(float4*)(arr + s0 * ARRS + G0) =
                make_float4(o0[0], o0[1], o0[2], o0[3]);
            *(float4*)(arr + (s0 + 1) * ARRS + G0) =
                make_float4(o1[0], o1[1], o1[2], o1[3]);
        }
        barn(barid, 256);

        // update: thread (su,u) and (su+4,u)
        {
            const float* a0 = arr + su * ARRS;
            float gi = a0[u], gf = a0[HH + u], gc = a0[2*HH + u], go = a0[3*HH + u];
            creg0 = gf * creg0 + gi * gc;
            hsm[KOFF(u) + su] = go * tanhft(creg0);
            const float* a1 = arr + (su + 4) * ARRS;
            gi = a1[u]; gf = a1[HH + u]; gc = a1[2*HH + u]; go = a1[3*HH + u];
            creg1 = gf * creg1 + gi * gc;
            hsm[KOFF(u) + su + 4] = go * tanhft(creg1);
        }
        barn(barid, 256);
    }

    // h_fwd -> last[:, 0:64]
    last[su * 2 * HH + u]       = hsm[KOFF(u) + su];
    last[(su + 4) * 2 * HH + u] = hsm[KOFF(u) + su + 4];

    // ---- backward LSTM: one step from zero state on x[T-1] ----
    {
        float wbb[4][5], bbr[4];
#pragma unroll
        for (int g = 0; g < 4; g++) {
#pragma unroll
            for (int f = 0; f < FF; f++) wbb[g][f] = Wih_b[(G0 + g) * FF + f];
            bbr[g] = bih_b[G0 + g] + bhh_b[G0 + g];
        }
        const float* xtA = xs + s0 * (TT * FF) + (TT - 1) * FF;
        const float* xtB = xtA + (TT * FF);
        float o0[4], o1[4];
#pragma unroll
        for (int g = 0; g < 4; g++) {
            float a0 = bbr[g], a1 = bbr[g];
#pragma unroll
            for (int f = 0; f < FF; f++) {
                a0 += xtA[f] * wbb[g][f];
                a1 += xtB[f] * wbb[g][f];
            }
            o0[g] = (gtype == 2) ? tanhft(a0) : sigm(a0);
            o1[g] = (gtype == 2) ? tanhft(a1) : sigm(a1);
        }
        *(float4*)(arr + s0 * ARRS + G0) =
            make_float4(o0[0], o0[1], o0[2], o0[3]);
        *(float4*)(arr + (s0 + 1) * ARRS + G0) =
            make_float4(o1[0], o1[1], o1[2], o1[3]);
    }
    barn(barid, 256);
#pragma unroll
    for (int p = 0; p < 2; p++) {
        int s = su + p * 4;
        const float* a = arr + s * ARRS;
        float gi = a[u], gc = a[2*HH + u], go = a[3*HH + u];
        last[s * 2 * HH + HH + u] = go * tanhft(gi * gc);   // f*c0 = 0
    }
    barn(barid, 256);

    // ---- fc0 + leaky (packed f32x2; weight row reused for both seqs) ----
    {
        const double2* w2 = (const double2*)(fc0_w + u * 2 * HH);
        const double2* la = (const double2*)(last + su * 2 * HH);
        const double2* lb = (const double2*)(last + (su + 4) * 2 * HH);
        unsigned long long a0 = 0ull, a1 = 0ull, b0 = 0ull, b1 = 0ull;
#pragma unroll
        for (int j = 0; j < 2 * HH / 4; j++) {
            double2 wv = w2[j];
            double2 va = la[j];
            double2 vb = lb[j];
            fma2(a0, D2L(va.x), D2L(wv.x));
            fma2(a1, D2L(va.y), D2L(wv.y));
            fma2(b0, D2L(vb.x), D2L(wv.x));
            fma2(b1, D2L(vb.y), D2L(wv.y));
        }
        float fb = fc0_b[u];
        outb[su * HH + u]       = leaky(fb + sum2(a0) + sum2(a1));
        outb[(su + 4) * HH + u] = leaky(fb + sum2(b0) + sum2(b1));
    }
    barn(barid, 256);

    // ---- epilogue scalars: one warp per sequence (3 dots fused) ----
    if (w < ns) {
        int sg = sbase + w;
        const float* o = outb + w * HH;
        float o_lo = o[lane], o_hi = o[lane + 32];
        float v0 = o_lo * fc3_w[lane]        + o_hi * fc3_w[lane + 32];
        float v1 = o_lo * pred_w[HH + lane]  + o_hi * pred_w[HH + lane + 32];
        float v2 = o_lo * pred_w[lane]       + o_hi * pred_w[lane + 32];
#pragma unroll
        for (int off = 16; off; off >>= 1) {
            v0 += __shfl_xor_sync(0xffffffffu, v0, off);
            v1 += __shfl_xor_sync(0xffffffffu, v1, off);
            v2 += __shfl_xor_sync(0xffffffffu, v2, off);
        }
        if (lane == 0) {
            g_tail[sg] = leaky(v0 + fc3_b[0]);
            g_q[sg]    = v1;
            g_p0[sg]   = v2;
        }
    }
}

// ---------------------------------------------------------------------------
// Persistent kernel: 152 CTAs x 512 threads (one per SM, one wave).
//   warps 0-7 : LSTM engine A (seqs 0..7 of this CTA) immediately.
//   warps 8-15: sparse relw (ticket + ballot), THEN LSTM engine B (rest).
// Grid barrier, then phase 3: masked softmax + prediction (warp per row).
// ---------------------------------------------------------------------------
__global__ __launch_bounds__(512, 1) void fused_kernel(
    const float* __restrict__ x,
    const float* __restrict__ enc,
    const float* __restrict__ rel_mask,
    const float* __restrict__ Wih_f, const float* __restrict__ Whh_f,
    const float* __restrict__ bih_f, const float* __restrict__ bhh_f,
    const float* __restrict__ Wih_b,
    const float* __restrict__ bih_b, const float* __restrict__ bhh_b,
    const float* __restrict__ fc0_w, const float* __restrict__ fc0_b,
    const float* __restrict__ fc1_w, const float* __restrict__ fc1_b,
    const float* __restrict__ fc3_w, const float* __restrict__ fc3_b,
    const float* __restrict__ pred_w, const float* __restrict__ pred_b,
    float* __restrict__ out)
{
    __shared__ float4 wsm[R4];                  // fc1 weights
    __shared__ float wihs[GG * FF];             // Wih_f staged
    __shared__ float bsumS[GG];                 // bih_f + bhh_f
    __shared__ float xsA[8 * TT * FF], xsB[8 * TT * FF];
    __shared__ __align__(16) float hsmA[544], hsmB[544];
    __shared__ __align__(16) float arrA[8 * ARRS], arrB[8 * ARRS];
    __shared__ __align__(16) float lastA[8 * 2 * HH], lastB[8 * 2 * HH];
    __shared__ float outA[8 * HH], outB[8 * HH];

    int cta = blockIdx.x;
    int tid = threadIdx.x;
    int wid = tid >> 5, lane = tid & 31;

    // Snapshot barrier generation BEFORE any arrival can happen this launch.
    unsigned int my_gen = *((volatile unsigned int*)&g_bar_gen);

    // Stage shared weights (fc1, Wih_f, bias sums) once, all 512 threads.
    {
        const float4* w4g = (const float4*)fc1_w;
        for (int i = tid; i < R4; i += 512) wsm[i] = w4g[i];
        for (int i = tid; i < GG * FF; i += 512) wihs[i] = Wih_f[i];
        for (int i = tid; i < GG; i += 512) bsumS[i] = bih_f[i] + bhh_f[i];
    }
    __syncthreads();

    // Sequence range: 2048 = 152*13 + 72  -> cnt = 13 or 14
    int base = 13 * cta + (cta < 72 ? cta : 72);
    int cnt  = 13 + (cta < 72 ? 1 : 0);

    if (wid < 8) {
        // ============ Half A: LSTM engine A (seqs 0..7) ====================
        lstm_engine(tid, base, 8, x, Whh_f, Wih_b, bih_b, bhh_b,
                    fc0_w, fc0_b, fc3_w, fc3_b, pred_w, wihs, bsumS,
                    xsA, hsmA, arrA, lastA, outA, /*barid=*/1);
    } else {
        // ============ Half B: sparse relw, then LSTM engine B ==============
        int t256 = tid - 256;
        {
            float fb = fc1_b[0];
            for (;;) {
                unsigned int tk;
                if (lane == 0) tk = atomicAdd(&g_ticket, 1u);
                tk = __shfl_sync(0xffffffffu, tk, 0);
                unsigned int c0 = tk * TPC;
                if (c0 >= NCHUNK) break;
#pragma unroll 1
                for (unsigned int c = c0; c < c0 + TPC && c < NCHUNK; c++) {
                    int pb = c * 32;
                    float mv = rel_mask[pb + lane];     // coalesced 128B load
                    unsigned act = __ballot_sync(0xffffffffu, mv == 0.f);
                    while (act) {
                        int b0 = __ffs(act) - 1; act &= act - 1;
                        int b1 = -1;
                        if (act) { b1 = __ffs(act) - 1; act &= act - 1; }
                        const float4* r0 = (const float4*)enc + (long long)(pb + b0) * R4;
                        float s0 = row_dot(r0, (const float4*)wsm, lane);
                        float s1 = 0.f;
                        if (b1 >= 0) {
                            const float4* r1 = (const float4*)enc + (long long)(pb + b1) * R4;
                            s1 = row_dot(r1, (const float4*)wsm, lane);
                        }
                        if (lane == 0) {
                            g_relw[pb + b0] = leaky(s0 + fb);
                            if (b1 >= 0) g_relw[pb + b1] = leaky(s1 + fb);
                        }
                    }
                }
            }
        }
        // LSTM engine B: remaining cnt-8 sequences (5 or 6)
        lstm_engine(t256, base + 8, cnt - 8, x, Whh_f, Wih_b, bih_b, bhh_b,
                    fc0_w, fc0_b, fc3_w, fc3_b, pred_w, wihs, bsumS,
                    xsB, hsmB, arrB, lastB, outB, /*barid=*/2);
    }

    // ===================== Grid-wide barrier ===============================
    __threadfence();                    // publish g_relw/g_tail/g_q/g_p0
    __syncthreads();                    // join the two halves
    if (tid == 0) {
        unsigned int old = atomicAdd(&g_bar_count, 1u);
        if (old == NSM - 1) {
            g_bar_count = 0;            // all CTAs have arrived
            g_ticket = 0;               // reset work ticket for next launch
            __threadfence();
            atomicAdd(&g_bar_gen, 1u);  // release
        }
        while (*((volatile unsigned int*)&g_bar_gen) == my_gen) { }
    }
    __syncthreads();
    __threadfence();                    // acquire

    // ====== Phase 3: masked softmax + prediction (one warp per row) ========
    if (wid < cnt) {
        int sg = base + wid;
        int b = sg >> 9, n = sg & (NN - 1);
        const float4* m4 = (const float4*)(rel_mask + (long long)n * NN);
        const float4* r4 = (const float4*)(g_relw  + (long long)n * NN);
        const float4* t4 = (const float4*)(g_tail + b * NN);
        const float4* q4 = (const float4*)(g_q    + b * NN);

        float4 l[4];
        float mx = -1e30f;
#pragma unroll
        for (int j = 0; j < 4; j++) {
            int idx = j * 32 + lane;
            float4 mv = m4[idx], rv = r4[idx], tv = t4[idx];
            l[j].x = mv.x + rv.x + tv.x;
            l[j].y = mv.y + rv.y + tv.y;
            l[j].z = mv.z + rv.z + tv.z;
            l[j].w = mv.w + rv.w + tv.w;
            mx = fmaxf(mx, fmaxf(fmaxf(l[j].x, l[j].y), fmaxf(l[j].z, l[j].w)));
        }
#pragma unroll
        for (int o = 16; o; o >>= 1) mx = fmaxf(mx, __shfl_xor_sync(0xffffffffu, mx, o));

        float se = 0.f, sq = 0.f;
#pragma unroll
        for (int j = 0; j < 4; j++) {
            int idx = j * 32 + lane;
            float4 qv = q4[idx];
            float e0 = __expf(l[j].x - mx);
            float e1 = __expf(l[j].y - mx);
            float e2 = __expf(l[j].z - mx);
            float e3 = __expf(l[j].w - mx);
            se += (e0 + e1) + (e2 + e3);
            sq += (e0 * qv.x + e1 * qv.y) + (e2 * qv.z + e3 * qv.w);
        }
#pragma unroll
        for (int o = 16; o; o >>= 1) {
            se += __shfl_xor_sync(0xffffffffu, se, o);
            sq += __shfl_xor_sync(0xffffffffu, sq, o);
        }
        if (lane == 0)
            out[sg] = leaky(g_p0[sg] + sq / se + pred_b[0]);
    }
}

// ---------------------------------------------------------------------------
extern "C" void kernel_launch(void* const* d_in, const int* in_sizes, int n_in,
                              void* d_out, int out_size) {
    const float* x      = (const float*)d_in[0];
    const float* enc    = (const float*)d_in[1];
    const float* mask   = (const float*)d_in[2];
    const float* Wih_f  = (const float*)d_in[3];
    const float* Whh_f  = (const float*)d_in[4];
    const float* bih_f  = (const float*)d_in[5];
    const float* bhh_f  = (const float*)d_in[6];
    const float* Wih_b  = (const float*)d_in[7];
    // d_in[8] (Whh_b) unused: backward LSTM runs exactly one step from zero state
    const float* bih_b  = (const float*)d_in[9];
    const float* bhh_b  = (const float*)d_in[10];
    const float* fc0_w  = (const float*)d_in[11];
    const float* fc0_b  = (const float*)d_in[12];
    const float* fc1_w  = (const float*)d_in[13];
    const float* fc1_b  = (const float*)d_in[14];
    // d_in[15..16] (fc2) unused: head term is constant over softmax axis
    const float* fc3_w  = (const float*)d_in[17];
    const float* fc3_b  = (const float*)d_in[18];
    const float* pred_w = (const float*)d_in[19];
    const float* pred_b = (const float*)d_in[20];
    float* out = (float*)d_out;

    fused_kernel<<<NSM, 512>>>(x, enc, mask, Wih_f, Whh_f, bih_f, bhh_f,
                               Wih_b, bih_b, bhh_b,
                               fc0_w, fc0_b, fc1_w, fc1_b, fc3_w, fc3_b,
                               pred_w, pred_b, out);
}